// round 7
// baseline (speedup 1.0000x reference)
#include <cuda_runtime.h>
#include <math.h>
#include <stdint.h>

#define Bn 4
#define Tn 8
#define Hn 256
#define Wn 256
#define Nn (Bn*Tn*Hn*Wn)   // 2,097,152

// params layout: 0:cc 1:ce 2:cw 3:cs 4:cn 5:cx(corner) 6:D
__device__ float g_params[7 * Nn];
__device__ float g_partLogD[2048];   // conv CTAs
__device__ float g_partXQX[2048];    // fused stencil CTAs

__device__ __forceinline__ float tanh_fast(float x) {
    float y; asm("tanh.approx.f32 %0, %1;" : "=f"(y) : "f"(x)); return y;
}
__device__ __forceinline__ uint32_t f2tf32(float f) {
    uint32_t u; asm("cvt.rna.tf32.f32 %0, %1;" : "=r"(u) : "f"(f)); return u;
}
__device__ __forceinline__ void mma_tf32(float c[4],
                                         uint32_t a0, uint32_t a1, uint32_t a2, uint32_t a3,
                                         uint32_t b0, uint32_t b1) {
    asm("mma.sync.aligned.m16n8k8.row.col.f32.tf32.tf32.f32 "
        "{%0,%1,%2,%3}, {%4,%5,%6,%7}, {%8,%9}, {%0,%1,%2,%3};"
        : "+f"(c[0]), "+f"(c[1]), "+f"(c[2]), "+f"(c[3])
        : "r"(a0), "r"(a1), "r"(a2), "r"(a3), "r"(b0), "r"(b1));
}

__device__ __forceinline__ float block_reduce_sum(float v) {
    __shared__ float red[8];
    #pragma unroll
    for (int o = 16; o > 0; o >>= 1) v += __shfl_down_sync(0xffffffffu, v, o);
    int lane = threadIdx.x & 31, wid = threadIdx.x >> 5;
    if (lane == 0) red[wid] = v;
    __syncthreads();
    if (wid == 0) {
        v = (lane < 8) ? red[lane] : 0.f;
        #pragma unroll
        for (int o = 4; o > 0; o >>= 1) v += __shfl_down_sync(0xffffffffu, v, o);
    }
    return v;  // valid on thread 0
}

// ---------------------------------------------------------------------------
// Conv 3x3 (8 -> 64 ch) as implicit GEMM on tensor cores (tf32 mma.sync).
// B fragments pre-swizzled per (tap, lane) into smem -> 4x LDS.128 per tap.
// CTA: 256 thr / 8 warps. Tile: 128 pixels x 64 oc, K = 72 (tap-major, ic inner).
// grid (2 w-segs, 256 h, 4 b) = 2048 CTAs.
// ---------------------------------------------------------------------------
__global__ __launch_bounds__(256)
void conv_mma_kernel(const float* __restrict__ x, const float* __restrict__ w) {
    __shared__ uint32_t xs[3][8][136];        // [kh][ic][col], tf32 bits
    __shared__ __align__(16) uint32_t Wf[9 * 32 * 20];  // per-lane B frags, stride 20 words

    const int tid  = threadIdx.x;
    const int lane = tid & 31;
    const int wid  = tid >> 5;
    const int seg  = blockIdx.x;           // 0..1
    const int h    = blockIdx.y;           // 0..255
    const int b    = blockIdx.z;           // 0..3
    const int w0   = seg * 128;

    // ---- stage pre-swizzled B fragments ----
    // e = n*2 + s; value = W[k = tap*8 + (q + 4s)][oc = n*8 + (lane>>2)]
    // where q = lane&3;  w layout: w[oc*72 + ic*9 + tap], ic = q + 4s.
    for (int j = tid; j < 9 * 32 * 16; j += 256) {
        int tap = j >> 9;          // /512
        int r   = j & 511;
        int ln  = r >> 4;
        int e   = r & 15;
        int n   = e >> 1;
        int s   = e & 1;
        int q   = ln & 3;
        int ocg = ln >> 2;
        int ic  = q + 4 * s;
        int oc  = n * 8 + ocg;
        Wf[(tap * 32 + ln) * 20 + e] = f2tf32(w[oc * 72 + ic * 9 + tap]);
    }

    // ---- stage x slab: rows h-1..h+1, cols w0-1..w0+128, 8 ic (tf32) ----
    const float* xb = x + b * Tn * Hn * Wn;
    for (int i = tid; i < 3 * 8 * 130; i += 256) {
        int r   = i / 1040;
        int rem = i - r * 1040;
        int ic  = rem / 130;
        int col = rem - ic * 130;
        int gh  = h - 1 + r;
        int gw  = w0 - 1 + col;
        float v = 0.f;
        if ((unsigned)gh < (unsigned)Hn && (unsigned)gw < (unsigned)Wn)
            v = xb[(ic * Hn + gh) * Wn + gw];
        xs[r][ic][col] = f2tf32(v);
    }
    __syncthreads();

    // ---- GEMM: each warp: m16 (pixels) x n64 (oc), K=72 ----
    const int q  = lane & 3;
    const int m0 = (wid << 4) + (lane >> 2);

    float acc[8][4];
    #pragma unroll
    for (int n = 0; n < 8; ++n)
        #pragma unroll
        for (int c = 0; c < 4; ++c) acc[n][c] = 0.f;

    const uint4* wf_lane = (const uint4*)&Wf[lane * 20];

    #pragma unroll
    for (int tap = 0; tap < 9; ++tap) {
        const int kh = tap / 3, kw = tap % 3;
        uint32_t a0 = xs[kh][q    ][m0 + kw];
        uint32_t a1 = xs[kh][q    ][m0 + 8 + kw];
        uint32_t a2 = xs[kh][q + 4][m0 + kw];
        uint32_t a3 = xs[kh][q + 4][m0 + 8 + kw];

        // 16 B values via 4x LDS.128 (stride 20 words -> 5 uint4)
        const uint4* wp = wf_lane + tap * (32 * 5);
        uint4 B0 = wp[0], B1 = wp[1], B2 = wp[2], B3 = wp[3];

        mma_tf32(acc[0], a0, a1, a2, a3, B0.x, B0.y);
        mma_tf32(acc[1], a0, a1, a2, a3, B0.z, B0.w);
        mma_tf32(acc[2], a0, a1, a2, a3, B1.x, B1.y);
        mma_tf32(acc[3], a0, a1, a2, a3, B1.z, B1.w);
        mma_tf32(acc[4], a0, a1, a2, a3, B2.x, B2.y);
        mma_tf32(acc[5], a0, a1, a2, a3, B2.z, B2.w);
        mma_tf32(acc[6], a0, a1, a2, a3, B3.x, B3.y);
        mma_tf32(acc[7], a0, a1, a2, a3, B3.z, B3.w);
    }

    // ---- epilogue: thread owns pixels {m0, m0+8}, t in {2q, 2q+1}, all 8 groups
    float local_logD = 0.f;
    #pragma unroll
    for (int pi = 0; pi < 2; ++pi) {
        int pix = m0 + 8 * pi;
        int wglob = w0 + pix;
        #pragma unroll
        for (int ti = 0; ti < 2; ++ti) {
            int t = 2 * q + ti;
            int cidx = 2 * pi + ti;
            float a0v = acc[0][cidx];   // kappa
            float a1v = acc[1][cidx];   // m1
            float a2v = acc[2][cidx];   // m2
            float a3v = acc[3][cidx];   // Hxx
            float a4v = acc[4][cidx];   // Hxy
            float a5v = acc[5][cidx];   // Hyx
            float a6v = acc[6][cidx];   // Hyy
            float a7v = acc[7][cidx];   // tau

            float kap  = 0.99f * (1.f / (1.f + __expf(-a0v))) + 0.01f;
            float kap2 = kap * kap;
            float hxx  = 0.99f * (1.f / (1.f + __expf(-a3v))) + 0.01f;
            float hyy  = 0.99f * (1.f / (1.f + __expf(-a6v))) + 0.01f;
            float hxys = 0.1f * (tanh_fast(a4v) + tanh_fast(a5v));
            float tau  = 9.9f * (1.f / (1.f + __expf(-a7v))) + 0.1f;
            float Dv   = 1.f / (tau * tau);
            local_logD += -2.f * __logf(tau);

            int idx = ((b * Tn + t) * Hn + h) * Wn + wglob;
            g_params[0 * Nn + idx] = kap2 + 2.f * hxx + 2.f * hyy;   // cc
            g_params[1 * Nn + idx] =  0.5f * a1v - hxx;              // ce
            g_params[2 * Nn + idx] = -0.5f * a1v - hxx;              // cw
            g_params[3 * Nn + idx] =  0.5f * a2v - hyy;              // cs
            g_params[4 * Nn + idx] = -0.5f * a2v - hyy;              // cn
            g_params[5 * Nn + idx] = -0.25f * hxys;                  // cx
            g_params[6 * Nn + idx] = Dv;
        }
    }

    __syncthreads();
    float s = block_reduce_sum(local_logD);
    if (tid == 0)
        g_partLogD[(blockIdx.z * 256 + blockIdx.y) * 2 + blockIdx.x] = s;
}

// ---------------------------------------------------------------------------
// Fused double stencil (unchanged — ~20us, DRAM-bound)
// ---------------------------------------------------------------------------
__global__ __launch_bounds__(256)
void fused_stencil_kernel(const float* __restrict__ x) {
    __shared__ float xs[36][36];
    __shared__ float ys[34][34];

    const int tid = threadIdx.x;
    const int tx  = tid & 31;
    const int ty  = tid >> 5;
    const int bt  = blockIdx.z;        // b*T + t
    const int t   = bt & (Tn - 1);
    const int h0  = blockIdx.y * 32;
    const int w0  = blockIdx.x * 32;
    const int base = bt * Hn * Wn;

    const float* up = x + base;
    for (int i = tid; i < 36 * 36; i += 256) {
        int ly = i / 36, lx = i - ly * 36;
        int gh = h0 - 2 + ly, gw = w0 - 2 + lx;
        xs[ly][lx] = ((unsigned)gh < (unsigned)Hn && (unsigned)gw < (unsigned)Wn)
                         ? up[gh * Wn + gw] : 0.f;
    }
    __syncthreads();

    for (int i = tid; i < 34 * 34; i += 256) {
        int ly = i / 34, lx = i - ly * 34;
        int gh = h0 - 1 + ly, gw = w0 - 1 + lx;
        float yv = 0.f;
        if ((unsigned)gh < (unsigned)Hn && (unsigned)gw < (unsigned)Wn) {
            int gidx = base + gh * Wn + gw;
            float c  = xs[ly + 1][lx + 1];
            float e  = xs[ly + 1][lx + 2];
            float wv = xs[ly + 1][lx + 0];
            float s  = xs[ly + 2][lx + 1];
            float n  = xs[ly + 0][lx + 1];
            float se = xs[ly + 2][lx + 2];
            float ne = xs[ly + 0][lx + 2];
            float sw = xs[ly + 2][lx + 0];
            float nw = xs[ly + 0][lx + 0];
            yv = g_params[0 * Nn + gidx] * c
               + g_params[1 * Nn + gidx] * e
               + g_params[2 * Nn + gidx] * wv
               + g_params[3 * Nn + gidx] * s
               + g_params[4 * Nn + gidx] * n
               + g_params[5 * Nn + gidx] * (se - ne - sw + nw);
        }
        ys[ly][lx] = yv;
    }
    __syncthreads();

    float local = 0.f;
    #pragma unroll
    for (int r = 0; r < 4; ++r) {
        int iy = ty * 4 + r;
        int gh = h0 + iy, gw = w0 + tx;
        int gidx = base + gh * Wn + gw;
        int ly = iy + 1, lx = tx + 1;

        float c  = ys[ly][lx];
        float e  = ys[ly][lx + 1];
        float wv = ys[ly][lx - 1];
        float s  = ys[ly + 1][lx];
        float n  = ys[ly - 1][lx];
        float se = ys[ly + 1][lx + 1];
        float ne = ys[ly - 1][lx + 1];
        float sw = ys[ly + 1][lx - 1];
        float nw = ys[ly - 1][lx - 1];

        float z = g_params[0 * Nn + gidx] * c
                + g_params[1 * Nn + gidx] * e
                + g_params[2 * Nn + gidx] * wv
                + g_params[3 * Nn + gidx] * s
                + g_params[4 * Nn + gidx] * n
                + g_params[5 * Nn + gidx] * (se - ne - sw + nw);

        float xc    = xs[iy + 2][tx + 2];
        float xprev = (t > 0) ? x[gidx - Hn * Wn] : 0.f;
        float rr = xc + z - xprev;
        local += g_params[6 * Nn + gidx] * rr * rr;
    }

    __syncthreads();
    float ssum = block_reduce_sum(local);
    if (threadIdx.x == 0)
        g_partXQX[(blockIdx.z * 8 + blockIdx.y) * 8 + blockIdx.x] = ssum;
}

// ---------------------------------------------------------------------------
// Final reduce of partials (double accumulation)
// ---------------------------------------------------------------------------
__global__ void final_kernel(float* out) {
    __shared__ double redq[32];
    __shared__ double redl[32];
    const int tid = threadIdx.x;   // 1024 threads
    double xq = (double)g_partXQX[tid]  + (double)g_partXQX[tid + 1024];
    double ld = (double)g_partLogD[tid] + (double)g_partLogD[tid + 1024];

    #pragma unroll
    for (int o = 16; o > 0; o >>= 1) {
        xq += __shfl_down_sync(0xffffffffu, xq, o);
        ld += __shfl_down_sync(0xffffffffu, ld, o);
    }
    int lane = tid & 31, wid = tid >> 5;
    if (lane == 0) { redq[wid] = xq; redl[wid] = ld; }
    __syncthreads();
    if (wid == 0) {
        xq = redq[lane];
        ld = redl[lane];
        #pragma unroll
        for (int o = 16; o > 0; o >>= 1) {
            xq += __shfl_down_sync(0xffffffffu, xq, o);
            ld += __shfl_down_sync(0xffffffffu, ld, o);
        }
        if (lane == 0) out[0] = (float)(0.5 * (xq - ld));
    }
}

extern "C" void kernel_launch(void* const* d_in, const int* in_sizes, int n_in,
                              void* d_out, int out_size) {
    const float* x = (const float*)d_in[0];
    const float* w = (const float*)d_in[1];
    float* out = (float*)d_out;

    conv_mma_kernel<<<dim3(2, 256, Bn), 256>>>(x, w);
    fused_stencil_kernel<<<dim3(8, 8, Bn * Tn), 256>>>(x);
    final_kernel<<<1, 1024>>>(out);
}

// round 8
// speedup vs baseline: 1.2322x; 1.2322x over previous
#include <cuda_runtime.h>
#include <math.h>
#include <stdint.h>

#define Bn 4
#define Tn 8
#define Hn 256
#define Wn 256
#define Nn (Bn*Tn*Hn*Wn)   // 2,097,152

// params layout: 0:cc 1:ce 2:cw 3:cs 4:cn 5:cx(corner) 6:D
__device__ float g_params[7 * Nn];
__device__ float g_partLogD[2048];   // conv CTAs
__device__ float g_partXQX[2048];    // fused stencil CTAs
__device__ uint32_t g_Wf[9 * 32 * 20];   // precomputed per-lane tf32 B fragments

__device__ __forceinline__ float tanh_fast(float x) {
    float y; asm("tanh.approx.f32 %0, %1;" : "=f"(y) : "f"(x)); return y;
}
__device__ __forceinline__ uint32_t f2tf32(float f) {
    uint32_t u; asm("cvt.rna.tf32.f32 %0, %1;" : "=r"(u) : "f"(f)); return u;
}
__device__ __forceinline__ void mma_tf32(float c[4],
                                         uint32_t a0, uint32_t a1, uint32_t a2, uint32_t a3,
                                         uint32_t b0, uint32_t b1) {
    asm("mma.sync.aligned.m16n8k8.row.col.f32.tf32.tf32.f32 "
        "{%0,%1,%2,%3}, {%4,%5,%6,%7}, {%8,%9}, {%0,%1,%2,%3};"
        : "+f"(c[0]), "+f"(c[1]), "+f"(c[2]), "+f"(c[3])
        : "r"(a0), "r"(a1), "r"(a2), "r"(a3), "r"(b0), "r"(b1));
}

__device__ __forceinline__ float block_reduce_sum(float v) {
    __shared__ float red[8];
    #pragma unroll
    for (int o = 16; o > 0; o >>= 1) v += __shfl_down_sync(0xffffffffu, v, o);
    int lane = threadIdx.x & 31, wid = threadIdx.x >> 5;
    if (lane == 0) red[wid] = v;
    __syncthreads();
    if (wid == 0) {
        v = (lane < 8) ? red[lane] : 0.f;
        #pragma unroll
        for (int o = 4; o > 0; o >>= 1) v += __shfl_down_sync(0xffffffffu, v, o);
    }
    return v;  // valid on thread 0
}

// ---------------------------------------------------------------------------
// One-time weight fragment swizzle (runs once, 1 CTA).
// e = n*2 + s; value = W[oc = n*8 + (lane>>2)][ic = (lane&3) + 4s][tap]
// ---------------------------------------------------------------------------
__global__ void precompute_wf_kernel(const float* __restrict__ w) {
    const int tid = threadIdx.x;
    for (int j = tid; j < 9 * 32 * 16; j += 256) {
        int tap = j >> 9;
        int r   = j & 511;
        int ln  = r >> 4;
        int e   = r & 15;
        int n   = e >> 1;
        int s   = e & 1;
        int q   = ln & 3;
        int ocg = ln >> 2;
        int ic  = q + 4 * s;
        int oc  = n * 8 + ocg;
        g_Wf[(tap * 32 + ln) * 20 + e] = f2tf32(w[oc * 72 + ic * 9 + tap]);
    }
    // zero the 4 pad words per (tap,lane) so staging copies defined data
    for (int j = tid; j < 9 * 32 * 4; j += 256) {
        int tl = j >> 2;
        int e  = 16 + (j & 3);
        g_Wf[tl * 20 + e] = 0;
    }
}

// ---------------------------------------------------------------------------
// Conv 3x3 (8 -> 64 ch) as implicit GEMM (tf32 mma.sync), cheap staging:
//  - weights: linear uint4 copy of precomputed g_Wf
//  - x slab: divide-free (warp -> 3 (kh,ic)-rows, lane -> cols)
// CTA: 256 thr / 8 warps. Tile: 128 pixels x 64 oc, K = 72.
// grid (2 w-segs, 256 h, 4 b) = 2048 CTAs.
// ---------------------------------------------------------------------------
__global__ __launch_bounds__(256)
void conv_mma_kernel(const float* __restrict__ x, const float* __restrict__ w) {
    __shared__ uint32_t xs[3][8][136];                    // [kh][ic][col], tf32 bits
    __shared__ __align__(16) uint32_t Wf[9 * 32 * 20];    // per-lane B frags

    const int tid  = threadIdx.x;
    const int lane = tid & 31;
    const int wid  = tid >> 5;
    const int seg  = blockIdx.x;           // 0..1
    const int h    = blockIdx.y;           // 0..255
    const int b    = blockIdx.z;           // 0..3
    const int w0   = seg * 128;

    // ---- stage weights: pure linear copy (1440 uint4) ----
    {
        const uint4* src = (const uint4*)g_Wf;
        uint4* dst = (uint4*)Wf;
        #pragma unroll
        for (int j = 0; j < 6; ++j) {
            int i = tid + j * 256;
            if (i < 1440) dst[i] = src[i];
        }
    }

    // ---- stage x slab, divide-free: 24 rows (kh,ic) x 130 cols ----
    {
        const float* xb = x + b * Tn * Hn * Wn;
        #pragma unroll
        for (int rr = 0; rr < 3; ++rr) {
            int row = wid * 3 + rr;        // 0..23
            int kh  = row >> 3;
            int ic  = row & 7;
            int gh  = h - 1 + kh;
            bool hok = (unsigned)gh < (unsigned)Hn;
            const float* rp = xb + (ic * Hn + gh) * Wn;
            #pragma unroll
            for (int it = 0; it < 5; ++it) {
                int col = lane + it * 32;
                if (col < 130) {
                    int gw = w0 - 1 + col;
                    float v = (hok && (unsigned)gw < (unsigned)Wn) ? rp[gw] : 0.f;
                    xs[kh][ic][col] = f2tf32(v);
                }
            }
        }
    }
    __syncthreads();

    // ---- GEMM: each warp: m16 (pixels) x n64 (oc), K=72 ----
    const int q  = lane & 3;
    const int m0 = (wid << 4) + (lane >> 2);

    float acc[8][4];
    #pragma unroll
    for (int n = 0; n < 8; ++n)
        #pragma unroll
        for (int c = 0; c < 4; ++c) acc[n][c] = 0.f;

    const uint4* wf_lane = (const uint4*)&Wf[lane * 20];

    #pragma unroll
    for (int tap = 0; tap < 9; ++tap) {
        const int kh = tap / 3, kw = tap % 3;
        uint32_t a0 = xs[kh][q    ][m0 + kw];
        uint32_t a1 = xs[kh][q    ][m0 + 8 + kw];
        uint32_t a2 = xs[kh][q + 4][m0 + kw];
        uint32_t a3 = xs[kh][q + 4][m0 + 8 + kw];

        const uint4* wp = wf_lane + tap * (32 * 5);
        uint4 B0 = wp[0], B1 = wp[1], B2 = wp[2], B3 = wp[3];

        mma_tf32(acc[0], a0, a1, a2, a3, B0.x, B0.y);
        mma_tf32(acc[1], a0, a1, a2, a3, B0.z, B0.w);
        mma_tf32(acc[2], a0, a1, a2, a3, B1.x, B1.y);
        mma_tf32(acc[3], a0, a1, a2, a3, B1.z, B1.w);
        mma_tf32(acc[4], a0, a1, a2, a3, B2.x, B2.y);
        mma_tf32(acc[5], a0, a1, a2, a3, B2.z, B2.w);
        mma_tf32(acc[6], a0, a1, a2, a3, B3.x, B3.y);
        mma_tf32(acc[7], a0, a1, a2, a3, B3.z, B3.w);
    }

    // ---- epilogue: thread owns pixels {m0, m0+8}, t in {2q, 2q+1}
    float local_logD = 0.f;
    #pragma unroll
    for (int pi = 0; pi < 2; ++pi) {
        int pix = m0 + 8 * pi;
        int wglob = w0 + pix;
        #pragma unroll
        for (int ti = 0; ti < 2; ++ti) {
            int t = 2 * q + ti;
            int cidx = 2 * pi + ti;
            float a0v = acc[0][cidx];   // kappa
            float a1v = acc[1][cidx];   // m1
            float a2v = acc[2][cidx];   // m2
            float a3v = acc[3][cidx];   // Hxx
            float a4v = acc[4][cidx];   // Hxy
            float a5v = acc[5][cidx];   // Hyx
            float a6v = acc[6][cidx];   // Hyy
            float a7v = acc[7][cidx];   // tau

            float kap  = 0.99f * (1.f / (1.f + __expf(-a0v))) + 0.01f;
            float kap2 = kap * kap;
            float hxx  = 0.99f * (1.f / (1.f + __expf(-a3v))) + 0.01f;
            float hyy  = 0.99f * (1.f / (1.f + __expf(-a6v))) + 0.01f;
            float hxys = 0.1f * (tanh_fast(a4v) + tanh_fast(a5v));
            float tau  = 9.9f * (1.f / (1.f + __expf(-a7v))) + 0.1f;
            float Dv   = 1.f / (tau * tau);
            local_logD += -2.f * __logf(tau);

            int idx = ((b * Tn + t) * Hn + h) * Wn + wglob;
            g_params[0 * Nn + idx] = kap2 + 2.f * hxx + 2.f * hyy;   // cc
            g_params[1 * Nn + idx] =  0.5f * a1v - hxx;              // ce
            g_params[2 * Nn + idx] = -0.5f * a1v - hxx;              // cw
            g_params[3 * Nn + idx] =  0.5f * a2v - hyy;              // cs
            g_params[4 * Nn + idx] = -0.5f * a2v - hyy;              // cn
            g_params[5 * Nn + idx] = -0.25f * hxys;                  // cx
            g_params[6 * Nn + idx] = Dv;
        }
    }

    __syncthreads();
    float s = block_reduce_sum(local_logD);
    if (tid == 0)
        g_partLogD[(blockIdx.z * 256 + blockIdx.y) * 2 + blockIdx.x] = s;
}

// ---------------------------------------------------------------------------
// Fused double stencil (unchanged — ~20us, DRAM-bound)
// ---------------------------------------------------------------------------
__global__ __launch_bounds__(256)
void fused_stencil_kernel(const float* __restrict__ x) {
    __shared__ float xs[36][36];
    __shared__ float ys[34][34];

    const int tid = threadIdx.x;
    const int tx  = tid & 31;
    const int ty  = tid >> 5;
    const int bt  = blockIdx.z;        // b*T + t
    const int t   = bt & (Tn - 1);
    const int h0  = blockIdx.y * 32;
    const int w0  = blockIdx.x * 32;
    const int base = bt * Hn * Wn;

    const float* up = x + base;
    for (int i = tid; i < 36 * 36; i += 256) {
        int ly = i / 36, lx = i - ly * 36;
        int gh = h0 - 2 + ly, gw = w0 - 2 + lx;
        xs[ly][lx] = ((unsigned)gh < (unsigned)Hn && (unsigned)gw < (unsigned)Wn)
                         ? up[gh * Wn + gw] : 0.f;
    }
    __syncthreads();

    for (int i = tid; i < 34 * 34; i += 256) {
        int ly = i / 34, lx = i - ly * 34;
        int gh = h0 - 1 + ly, gw = w0 - 1 + lx;
        float yv = 0.f;
        if ((unsigned)gh < (unsigned)Hn && (unsigned)gw < (unsigned)Wn) {
            int gidx = base + gh * Wn + gw;
            float c  = xs[ly + 1][lx + 1];
            float e  = xs[ly + 1][lx + 2];
            float wv = xs[ly + 1][lx + 0];
            float s  = xs[ly + 2][lx + 1];
            float n  = xs[ly + 0][lx + 1];
            float se = xs[ly + 2][lx + 2];
            float ne = xs[ly + 0][lx + 2];
            float sw = xs[ly + 2][lx + 0];
            float nw = xs[ly + 0][lx + 0];
            yv = g_params[0 * Nn + gidx] * c
               + g_params[1 * Nn + gidx] * e
               + g_params[2 * Nn + gidx] * wv
               + g_params[3 * Nn + gidx] * s
               + g_params[4 * Nn + gidx] * n
               + g_params[5 * Nn + gidx] * (se - ne - sw + nw);
        }
        ys[ly][lx] = yv;
    }
    __syncthreads();

    float local = 0.f;
    #pragma unroll
    for (int r = 0; r < 4; ++r) {
        int iy = ty * 4 + r;
        int gh = h0 + iy, gw = w0 + tx;
        int gidx = base + gh * Wn + gw;
        int ly = iy + 1, lx = tx + 1;

        float c  = ys[ly][lx];
        float e  = ys[ly][lx + 1];
        float wv = ys[ly][lx - 1];
        float s  = ys[ly + 1][lx];
        float n  = ys[ly - 1][lx];
        float se = ys[ly + 1][lx + 1];
        float ne = ys[ly - 1][lx + 1];
        float sw = ys[ly + 1][lx - 1];
        float nw = ys[ly - 1][lx - 1];

        float z = g_params[0 * Nn + gidx] * c
                + g_params[1 * Nn + gidx] * e
                + g_params[2 * Nn + gidx] * wv
                + g_params[3 * Nn + gidx] * s
                + g_params[4 * Nn + gidx] * n
                + g_params[5 * Nn + gidx] * (se - ne - sw + nw);

        float xc    = xs[iy + 2][tx + 2];
        float xprev = (t > 0) ? x[gidx - Hn * Wn] : 0.f;
        float rr = xc + z - xprev;
        local += g_params[6 * Nn + gidx] * rr * rr;
    }

    __syncthreads();
    float ssum = block_reduce_sum(local);
    if (threadIdx.x == 0)
        g_partXQX[(blockIdx.z * 8 + blockIdx.y) * 8 + blockIdx.x] = ssum;
}

// ---------------------------------------------------------------------------
// Final reduce of partials (double accumulation)
// ---------------------------------------------------------------------------
__global__ void final_kernel(float* out) {
    __shared__ double redq[32];
    __shared__ double redl[32];
    const int tid = threadIdx.x;   // 1024 threads
    double xq = (double)g_partXQX[tid]  + (double)g_partXQX[tid + 1024];
    double ld = (double)g_partLogD[tid] + (double)g_partLogD[tid + 1024];

    #pragma unroll
    for (int o = 16; o > 0; o >>= 1) {
        xq += __shfl_down_sync(0xffffffffu, xq, o);
        ld += __shfl_down_sync(0xffffffffu, ld, o);
    }
    int lane = tid & 31, wid = tid >> 5;
    if (lane == 0) { redq[wid] = xq; redl[wid] = ld; }
    __syncthreads();
    if (wid == 0) {
        xq = redq[lane];
        ld = redl[lane];
        #pragma unroll
        for (int o = 16; o > 0; o >>= 1) {
            xq += __shfl_down_sync(0xffffffffu, xq, o);
            ld += __shfl_down_sync(0xffffffffu, ld, o);
        }
        if (lane == 0) out[0] = (float)(0.5 * (xq - ld));
    }
}

extern "C" void kernel_launch(void* const* d_in, const int* in_sizes, int n_in,
                              void* d_out, int out_size) {
    const float* x = (const float*)d_in[0];
    const float* w = (const float*)d_in[1];
    float* out = (float*)d_out;

    precompute_wf_kernel<<<1, 256>>>(w);
    conv_mma_kernel<<<dim3(2, 256, Bn), 256>>>(x, w);
    fused_stencil_kernel<<<dim3(8, 8, Bn * Tn), 256>>>(x);
    final_kernel<<<1, 1024>>>(out);
}